// round 2
// baseline (speedup 1.0000x reference)
#include <cuda_runtime.h>
#include <cuda_bf16.h>

// ---------------------------------------------------------------------------
// Problem: out[n] = m_left^T @ (x[n] * diag_scale) @ m_right, n = 0..8191
//   m_left  = Cayley(u_left)  @ diag(diag_left)  @ Cayley(v_left)
//   m_right = Cayley(u_right) @ diag(diag_right) @ Cayley(v_right)
//   Cayley(X): A = tril(X,-1) - tril(X,-1)^T;  Q = (I - A/2)^{-1}(I + A/2)
//
// Identity split for precision with tf32 MMA:
//   E_L^T = m_left^T - I,  E_R = m_right - I
//   Y   = Xs + Xs @ E_R
//   out = Y  + E_L^T @ Y
// The identity path stays fp32-exact; tf32 rounding only hits the small
// correction terms.
// ---------------------------------------------------------------------------

__device__ float g_Q[4 * 4096];    // Cayley results: [u_l, v_l, u_r, v_r]
__device__ float g_ELT[4096];      // (m_left^T - I)[l][i]
__device__ float g_ER[4096];       // (m_right  - I)[j][r]

// ---------------------------------------------------------------------------
// Kernel 1: 4 blocks, each computes one Cayley transform via Gauss-Jordan
// (I - A/2 has symmetric part I -> well conditioned, no pivoting needed).
// Augmented system [P | I + A/2], 64 x 128, smem stride 129.
// ---------------------------------------------------------------------------
__global__ void __launch_bounds__(512) cayley_kernel(
    const float* __restrict__ ul, const float* __restrict__ vl,
    const float* __restrict__ ur, const float* __restrict__ vr)
{
    __shared__ float M[64 * 129];
    __shared__ float fcol[64];
    const float* src = (blockIdx.x == 0) ? ul : (blockIdx.x == 1) ? vl
                     : (blockIdx.x == 2) ? ur : vr;
    int tid = threadIdx.x;

    for (int idx = tid; idx < 4096; idx += 512) {
        int i = idx >> 6, j = idx & 63;
        float a = 0.0f;
        if (i > j)      a =  src[i * 64 + j];
        else if (i < j) a = -src[j * 64 + i];
        float d = (i == j) ? 1.0f : 0.0f;
        M[i * 129 + j]      = d - 0.5f * a;   // P = I - A/2
        M[i * 129 + 64 + j] = d + 0.5f * a;   // RHS = I + A/2
    }
    __syncthreads();

    for (int p = 0; p < 64; p++) {
        float piv = M[p * 129 + p];
        if (tid < 64) fcol[tid] = (tid == p) ? 0.0f : M[tid * 129 + p];
        __syncthreads();
        float pinv = 1.0f / piv;
        for (int j = tid; j < 128; j += 512) M[p * 129 + j] *= pinv;
        __syncthreads();
        for (int idx = tid; idx < 64 * 128; idx += 512) {
            int r = idx >> 7, j = idx & 127;
            if (r != p) M[r * 129 + j] -= fcol[r] * M[p * 129 + j];
        }
        __syncthreads();
    }

    float* dst = g_Q + blockIdx.x * 4096;
    for (int idx = tid; idx < 4096; idx += 512) {
        int i = idx >> 6, j = idx & 63;
        dst[idx] = M[i * 129 + 64 + j];   // Q = P^{-1} RHS
    }
}

// ---------------------------------------------------------------------------
// Kernel 2: 2 blocks. Block 0 -> E_L^T, block 1 -> E_R.
//   m[i][j] = sum_k Qu[i][k] * d[k] * Qv[k][j]
//   g_ELT[l*64+i] = m_left[i][l] - (i==l)
//   g_ER [j*64+r] = m_right[j][r] - (j==r)
// ---------------------------------------------------------------------------
__global__ void __launch_bounds__(256) combine_kernel(
    const float* __restrict__ dl, const float* __restrict__ dr)
{
    __shared__ float Qa[64 * 65], Qb[64 * 65], dsh[64];
    int b = blockIdx.x, tid = threadIdx.x;
    const float* qa = g_Q + (b ? 2 : 0) * 4096;
    const float* qb = g_Q + (b ? 3 : 1) * 4096;
    const float* dg = b ? dr : dl;

    for (int idx = tid; idx < 4096; idx += 256) {
        int i = idx >> 6, j = idx & 63;
        Qa[i * 65 + j] = qa[idx];
        Qb[i * 65 + j] = qb[idx];
    }
    if (tid < 64) dsh[tid] = dg[tid];
    __syncthreads();

    float* dst = b ? g_ER : g_ELT;
    for (int idx = tid; idx < 4096; idx += 256) {
        int row = idx >> 6, col = idx & 63;
        int mi = b ? row : col;   // row index into m
        int mj = b ? col : row;   // col index into m
        float s = 0.0f;
        #pragma unroll 8
        for (int k = 0; k < 64; k++)
            s += Qa[mi * 65 + k] * (dsh[k] * Qb[k * 65 + mj]);
        if (mi == mj) s -= 1.0f;
        dst[idx] = s;
    }
}

// ---------------------------------------------------------------------------
// Main batched transform kernel: tf32 mma.m16n8k8, 4 matrices per block.
// ---------------------------------------------------------------------------
__device__ __forceinline__ unsigned f2tf32(float f) {
    unsigned u;
    asm("cvt.rna.tf32.f32 %0, %1;" : "=r"(u) : "f"(f));
    return u;
}

__device__ __forceinline__ void mma_tf32(float c[4],
    unsigned a0, unsigned a1, unsigned a2, unsigned a3,
    unsigned b0, unsigned b1)
{
    asm volatile(
        "mma.sync.aligned.m16n8k8.row.col.f32.tf32.tf32.f32 "
        "{%0,%1,%2,%3}, {%4,%5,%6,%7}, {%8,%9}, {%0,%1,%2,%3};\n"
        : "+f"(c[0]), "+f"(c[1]), "+f"(c[2]), "+f"(c[3])
        : "r"(a0), "r"(a1), "r"(a2), "r"(a3), "r"(b0), "r"(b1));
}

#define XS_STRIDE 68   // (4*gi + ti) unique mod 32 -> conflict-free A-frag LDS

__global__ void __launch_bounds__(256, 4) trans_kernel(
    const float* __restrict__ x, const float* __restrict__ dscale,
    float* __restrict__ out)
{
    extern __shared__ float sm[];
    float*    Xs   = sm;                                    // 64 x 68 fp32
    unsigned* sELT = (unsigned*)(sm + 64 * XS_STRIDE);      // tf32 bits
    unsigned* sER  = (unsigned*)(sm + 2 * 64 * XS_STRIDE);  // tf32 bits

    int tid = threadIdx.x;
    for (int idx = tid; idx < 4096; idx += 256) {
        int i = idx >> 6, j = idx & 63;
        sELT[i * XS_STRIDE + j] = f2tf32(g_ELT[idx]);
        sER [i * XS_STRIDE + j] = f2tf32(g_ER[idx]);
    }

    float ds[16];
    #pragma unroll
    for (int t = 0; t < 16; t++) ds[t] = dscale[tid + t * 256];

    int w = tid >> 5, lane = tid & 31, gi = lane >> 2, ti = lane & 3;
    int r0 = (w >> 1) * 16, c0 = (w & 1) * 32;
    int base = blockIdx.x * 4 * 4096;
    __syncthreads();

    for (int it = 0; it < 4; it++) {
        int xb = base + it * 4096;
        // ---- load + diag scale (coalesced) ----
        #pragma unroll
        for (int t = 0; t < 16; t++) {
            int idx = tid + t * 256;
            Xs[(idx >> 6) * XS_STRIDE + (idx & 63)] = x[xb + idx] * ds[t];
        }
        __syncthreads();

        // ---- Stage 1: Y = Xs + Xs @ E_R (acc preloaded with Xs) ----
        float acc[4][4];
        #pragma unroll
        for (int nt = 0; nt < 4; nt++) {
            int col = c0 + nt * 8 + 2 * ti;
            acc[nt][0] = Xs[(r0 + gi)     * XS_STRIDE + col];
            acc[nt][1] = Xs[(r0 + gi)     * XS_STRIDE + col + 1];
            acc[nt][2] = Xs[(r0 + gi + 8) * XS_STRIDE + col];
            acc[nt][3] = Xs[(r0 + gi + 8) * XS_STRIDE + col + 1];
        }
        #pragma unroll
        for (int kt = 0; kt < 8; kt++) {
            int k0 = kt * 8;
            unsigned a0 = f2tf32(Xs[(r0 + gi)     * XS_STRIDE + k0 + ti]);
            unsigned a1 = f2tf32(Xs[(r0 + gi + 8) * XS_STRIDE + k0 + ti]);
            unsigned a2 = f2tf32(Xs[(r0 + gi)     * XS_STRIDE + k0 + ti + 4]);
            unsigned a3 = f2tf32(Xs[(r0 + gi + 8) * XS_STRIDE + k0 + ti + 4]);
            #pragma unroll
            for (int nt = 0; nt < 4; nt++) {
                unsigned b0 = sER[(k0 + ti)     * XS_STRIDE + c0 + nt * 8 + gi];
                unsigned b1 = sER[(k0 + ti + 4) * XS_STRIDE + c0 + nt * 8 + gi];
                mma_tf32(acc[nt], a0, a1, a2, a3, b0, b1);
            }
        }
        __syncthreads();
        // ---- write Y in place over Xs ----
        #pragma unroll
        for (int nt = 0; nt < 4; nt++) {
            int col = c0 + nt * 8 + 2 * ti;
            Xs[(r0 + gi)     * XS_STRIDE + col]     = acc[nt][0];
            Xs[(r0 + gi)     * XS_STRIDE + col + 1] = acc[nt][1];
            Xs[(r0 + gi + 8) * XS_STRIDE + col]     = acc[nt][2];
            Xs[(r0 + gi + 8) * XS_STRIDE + col + 1] = acc[nt][3];
        }
        __syncthreads();

        // ---- Stage 2: out = Y + E_L^T @ Y (acc preloaded with Y) ----
        float acc2[4][4];
        #pragma unroll
        for (int nt = 0; nt < 4; nt++) {
            int col = c0 + nt * 8 + 2 * ti;
            acc2[nt][0] = Xs[(r0 + gi)     * XS_STRIDE + col];
            acc2[nt][1] = Xs[(r0 + gi)     * XS_STRIDE + col + 1];
            acc2[nt][2] = Xs[(r0 + gi + 8) * XS_STRIDE + col];
            acc2[nt][3] = Xs[(r0 + gi + 8) * XS_STRIDE + col + 1];
        }
        #pragma unroll
        for (int kt = 0; kt < 8; kt++) {
            int k0 = kt * 8;
            unsigned a0 = sELT[(r0 + gi)     * XS_STRIDE + k0 + ti];
            unsigned a1 = sELT[(r0 + gi + 8) * XS_STRIDE + k0 + ti];
            unsigned a2 = sELT[(r0 + gi)     * XS_STRIDE + k0 + ti + 4];
            unsigned a3 = sELT[(r0 + gi + 8) * XS_STRIDE + k0 + ti + 4];
            #pragma unroll
            for (int nt = 0; nt < 4; nt++) {
                unsigned b0 = f2tf32(Xs[(k0 + ti)     * XS_STRIDE + c0 + nt * 8 + gi]);
                unsigned b1 = f2tf32(Xs[(k0 + ti + 4) * XS_STRIDE + c0 + nt * 8 + gi]);
                mma_tf32(acc2[nt], a0, a1, a2, a3, b0, b1);
            }
        }
        // ---- store (float2, coalesced-ish) ----
        #pragma unroll
        for (int nt = 0; nt < 4; nt++) {
            int col = c0 + nt * 8 + 2 * ti;
            float2 v0 = make_float2(acc2[nt][0], acc2[nt][1]);
            float2 v1 = make_float2(acc2[nt][2], acc2[nt][3]);
            *(float2*)&out[xb + (r0 + gi)     * 64 + col] = v0;
            *(float2*)&out[xb + (r0 + gi + 8) * 64 + col] = v1;
        }
        __syncthreads();
    }
}

// ---------------------------------------------------------------------------
// Launch
// ---------------------------------------------------------------------------
extern "C" void kernel_launch(void* const* d_in, const int* in_sizes, int n_in,
                              void* d_out, int out_size)
{
    const float* x   = (const float*)d_in[0];
    const float* ul  = (const float*)d_in[1];
    const float* vl  = (const float*)d_in[2];
    const float* dl  = (const float*)d_in[3];
    const float* ur  = (const float*)d_in[4];
    const float* vr  = (const float*)d_in[5];
    const float* dr  = (const float*)d_in[6];
    const float* dsc = (const float*)d_in[7];
    float* out = (float*)d_out;

    cayley_kernel<<<4, 512>>>(ul, vl, ur, vr);
    combine_kernel<<<2, 256>>>(dl, dr);

    static const int kSmem = 3 * 64 * XS_STRIDE * (int)sizeof(float); // 52224
    cudaFuncSetAttribute(trans_kernel,
                         cudaFuncAttributeMaxDynamicSharedMemorySize, kSmem);
    trans_kernel<<<2048, 256, kSmem>>>(x, dsc, out);
}

// round 4
// speedup vs baseline: 1.2416x; 1.2416x over previous
#include <cuda_runtime.h>
#include <cuda_bf16.h>

// ---------------------------------------------------------------------------
// out[n] = m_left^T @ (x[n] * diag_scale) @ m_right, n = 0..8191 (64x64 each)
// Identity split for tf32 precision:
//   E_L^T = m_left^T - I,  E_R = m_right - I
//   Y   = Xs + Xs @ E_R ;  out = Y + E_L^T @ Y
// Cayley via truncated Neumann polynomial (||A/2|| ~ 0.17):
//   Q = (I + 2M + M^2)(I + M^2)(I + M^4),  M = A/2,  err ~ ||M||^8 ~ 1e-6
// ---------------------------------------------------------------------------

__device__ float g_Q[4 * 4096];    // Cayley results: [u_l, v_l, u_r, v_r]
__device__ float g_ELT[4096];      // (m_left^T - I)[l][i]
__device__ float g_ER[4096];       // (m_right  - I)[j][r]

#define CST 68   // smem stride for 64-col matrices (float4-aligned, conflict-free)

// ---------------------------------------------------------------------------
// Kernel 1: 4 blocks x 1024 threads; polynomial Cayley with 4 smem matmuls.
// Buffers (dynamic smem, stride CST): B0=M->L, B1=m2->Q, B2=m4, B3=T
// ---------------------------------------------------------------------------
__device__ __forceinline__ void mm64(float* C, const float* A, const float* B,
                                     bool addA, int tid)
{
    int r  = tid >> 4;          // 0..63
    int c0 = (tid & 15) * 4;    // 0..60
    float acc[4];
    if (addA) {
        float4 a4 = *(const float4*)&A[r * CST + c0];
        acc[0] = a4.x; acc[1] = a4.y; acc[2] = a4.z; acc[3] = a4.w;
    } else {
        acc[0] = acc[1] = acc[2] = acc[3] = 0.0f;
    }
    #pragma unroll 4
    for (int k = 0; k < 64; k++) {
        float a = A[r * CST + k];
        float4 b4 = *(const float4*)&B[k * CST + c0];
        acc[0] += a * b4.x; acc[1] += a * b4.y;
        acc[2] += a * b4.z; acc[3] += a * b4.w;
    }
    *(float4*)&C[r * CST + c0] = make_float4(acc[0], acc[1], acc[2], acc[3]);
    __syncthreads();
}

__global__ void __launch_bounds__(1024) cayley_kernel(
    const float* __restrict__ ul, const float* __restrict__ vl,
    const float* __restrict__ ur, const float* __restrict__ vr)
{
    extern __shared__ float cs[];
    float* B0 = cs;                 // M, later L
    float* B1 = cs + 64 * CST;      // m2, later Q
    float* B2 = cs + 2 * 64 * CST;  // m4
    float* B3 = cs + 3 * 64 * CST;  // T
    const float* src = (blockIdx.x == 0) ? ul : (blockIdx.x == 1) ? vl
                     : (blockIdx.x == 2) ? ur : vr;
    int tid = threadIdx.x;

    // M = A/2,  A = tril(X,-1) - tril(X,-1)^T
    for (int idx = tid; idx < 4096; idx += 1024) {
        int i = idx >> 6, j = idx & 63;
        float a = 0.0f;
        if (i > j)      a =  src[i * 64 + j];
        else if (i < j) a = -src[j * 64 + i];
        B0[i * CST + j] = 0.5f * a;
    }
    __syncthreads();

    mm64(B1, B0, B0, false, tid);   // m2 = M*M
    mm64(B2, B1, B1, false, tid);   // m4 = m2*m2

    // L = I + 2M + m2  (in place over M)
    {
        int q = tid;                // 1024 float4 slots
        int r = q >> 4, c0 = (q & 15) * 4;
        float4 m  = *(float4*)&B0[r * CST + c0];
        float4 m2 = *(float4*)&B1[r * CST + c0];
        float4 L = make_float4(2.0f * m.x + m2.x, 2.0f * m.y + m2.y,
                               2.0f * m.z + m2.z, 2.0f * m.w + m2.w);
        if (r == c0)     L.x += 1.0f;
        if (r == c0 + 1) L.y += 1.0f;
        if (r == c0 + 2) L.z += 1.0f;
        if (r == c0 + 3) L.w += 1.0f;
        *(float4*)&B0[r * CST + c0] = L;
    }
    __syncthreads();

    mm64(B3, B0, B1, true, tid);    // T = L + L*m2
    mm64(B1, B3, B2, true, tid);    // Q = T + T*m4

    float* dst = g_Q + blockIdx.x * 4096;
    for (int idx = tid; idx < 4096; idx += 1024)
        dst[idx] = B1[(idx >> 6) * CST + (idx & 63)];
}

// ---------------------------------------------------------------------------
// Kernel 2: 2 blocks. Block 0 -> E_L^T, block 1 -> E_R.
// ---------------------------------------------------------------------------
__global__ void __launch_bounds__(256) combine_kernel(
    const float* __restrict__ dl, const float* __restrict__ dr)
{
    __shared__ float Qa[64 * 65], Qb[64 * 65], dsh[64];
    int b = blockIdx.x, tid = threadIdx.x;
    const float* qa = g_Q + (b ? 2 : 0) * 4096;
    const float* qb = g_Q + (b ? 3 : 1) * 4096;
    const float* dg = b ? dr : dl;

    for (int idx = tid; idx < 4096; idx += 256) {
        int i = idx >> 6, j = idx & 63;
        Qa[i * 65 + j] = qa[idx];
        Qb[i * 65 + j] = qb[idx];
    }
    if (tid < 64) dsh[tid] = dg[tid];
    __syncthreads();

    float* dst = b ? g_ER : g_ELT;
    for (int idx = tid; idx < 4096; idx += 256) {
        int row = idx >> 6, col = idx & 63;
        int mi = b ? row : col;
        int mj = b ? col : row;
        float s = 0.0f;
        #pragma unroll 8
        for (int k = 0; k < 64; k++)
            s += Qa[mi * 65 + k] * (dsh[k] * Qb[k * 65 + mj]);
        if (mi == mj) s -= 1.0f;
        dst[idx] = s;
    }
}

// ---------------------------------------------------------------------------
// Main batched transform: tf32 mma.m16n8k8, 4 matrices/block,
// E_R fragments in registers, double-buffered Xs, 2 barriers per matrix.
// ---------------------------------------------------------------------------
__device__ __forceinline__ unsigned f2tf32(float f) {
    unsigned u;
    asm("cvt.rna.tf32.f32 %0, %1;" : "=r"(u) : "f"(f));
    return u;
}

__device__ __forceinline__ void mma_tf32(float c[4],
    unsigned a0, unsigned a1, unsigned a2, unsigned a3,
    unsigned b0, unsigned b1)
{
    asm volatile(
        "mma.sync.aligned.m16n8k8.row.col.f32.tf32.tf32.f32 "
        "{%0,%1,%2,%3}, {%4,%5,%6,%7}, {%8,%9}, {%0,%1,%2,%3};\n"
        : "+f"(c[0]), "+f"(c[1]), "+f"(c[2]), "+f"(c[3])
        : "r"(a0), "r"(a1), "r"(a2), "r"(a3), "r"(b0), "r"(b1));
}

__global__ void __launch_bounds__(256, 2) trans_kernel(
    const float* __restrict__ x, const float* __restrict__ dscale,
    float* __restrict__ out)
{
    extern __shared__ float sm[];
    float*    Xs0  = sm;                         // 64 x CST
    float*    Xs1  = sm + 64 * CST;
    float*    Ys   = sm + 2 * 64 * CST;
    unsigned* sELT = (unsigned*)(sm + 3 * 64 * CST);

    int tid = threadIdx.x;
    int w = tid >> 5, lane = tid & 31, gi = lane >> 2, ti = lane & 3;
    int r0 = (w >> 1) * 16, c0 = (w & 1) * 32;

    // E_L^T (tf32) into smem
    for (int idx = tid; idx < 4096; idx += 256)
        sELT[(idx >> 6) * CST + (idx & 63)] = f2tf32(g_ELT[idx]);

    // E_R B-fragments into registers (fixed for whole kernel)
    unsigned erf[8][4][2];
    #pragma unroll
    for (int kt = 0; kt < 8; kt++)
        #pragma unroll
        for (int nt = 0; nt < 4; nt++) {
            erf[kt][nt][0] = f2tf32(g_ER[(kt * 8 + ti)     * 64 + c0 + nt * 8 + gi]);
            erf[kt][nt][1] = f2tf32(g_ER[(kt * 8 + ti + 4) * 64 + c0 + nt * 8 + gi]);
        }

    // diag scale cached (float4 layout matching x loads)
    float4 dsq[4];
    #pragma unroll
    for (int t = 0; t < 4; t++) dsq[t] = ((const float4*)dscale)[tid + t * 256];

    int base = blockIdx.x * 4 * 4096;

    // prologue: matrix 0 -> Xs0
    {
        const float4* xp = (const float4*)(x + base);
        #pragma unroll
        for (int t = 0; t < 4; t++) {
            int q = tid + t * 256;
            float4 v = xp[q];
            v.x *= dsq[t].x; v.y *= dsq[t].y; v.z *= dsq[t].z; v.w *= dsq[t].w;
            *(float4*)&Xs0[(q >> 4) * CST + (q & 15) * 4] = v;
        }
    }
    __syncthreads();

    for (int it = 0; it < 4; it++) {
        float* Xc = (it & 1) ? Xs1 : Xs0;
        float* Xn = (it & 1) ? Xs0 : Xs1;
        int xb = base + it * 4096;

        // ---- Stage 1: Y = Xs + Xs @ E_R (acc preloaded with Xs) ----
        float acc[4][4];
        #pragma unroll
        for (int nt = 0; nt < 4; nt++) {
            int col = c0 + nt * 8 + 2 * ti;
            acc[nt][0] = Xc[(r0 + gi)     * CST + col];
            acc[nt][1] = Xc[(r0 + gi)     * CST + col + 1];
            acc[nt][2] = Xc[(r0 + gi + 8) * CST + col];
            acc[nt][3] = Xc[(r0 + gi + 8) * CST + col + 1];
        }
        #pragma unroll
        for (int kt = 0; kt < 8; kt++) {
            int k0 = kt * 8;
            unsigned a0 = f2tf32(Xc[(r0 + gi)     * CST + k0 + ti]);
            unsigned a1 = f2tf32(Xc[(r0 + gi + 8) * CST + k0 + ti]);
            unsigned a2 = f2tf32(Xc[(r0 + gi)     * CST + k0 + ti + 4]);
            unsigned a3 = f2tf32(Xc[(r0 + gi + 8) * CST + k0 + ti + 4]);
            #pragma unroll
            for (int nt = 0; nt < 4; nt++)
                mma_tf32(acc[nt], a0, a1, a2, a3, erf[kt][nt][0], erf[kt][nt][1]);
        }
        // write Y (separate buffer; this warp's C tile -> consumed cross-warp)
        #pragma unroll
        for (int nt = 0; nt < 4; nt++) {
            int col = c0 + nt * 8 + 2 * ti;
            *(float2*)&Ys[(r0 + gi)     * CST + col] = make_float2(acc[nt][0], acc[nt][1]);
            *(float2*)&Ys[(r0 + gi + 8) * CST + col] = make_float2(acc[nt][2], acc[nt][3]);
        }

        // prefetch next matrix into registers (latency hidden by stage 2)
        float4 xq[4];
        if (it < 3) {
            const float4* xp = (const float4*)(x + base + (it + 1) * 4096);
            #pragma unroll
            for (int t = 0; t < 4; t++) xq[t] = xp[tid + t * 256];
        }
        __syncthreads();

        // ---- Stage 2: out = Y + E_L^T @ Y  (acc already holds Y!) ----
        #pragma unroll
        for (int kt = 0; kt < 8; kt++) {
            int k0 = kt * 8;
            unsigned a0 = sELT[(r0 + gi)     * CST + k0 + ti];
            unsigned a1 = sELT[(r0 + gi + 8) * CST + k0 + ti];
            unsigned a2 = sELT[(r0 + gi)     * CST + k0 + ti + 4];
            unsigned a3 = sELT[(r0 + gi + 8) * CST + k0 + ti + 4];
            #pragma unroll
            for (int nt = 0; nt < 4; nt++) {
                unsigned b0 = f2tf32(Ys[(k0 + ti)     * CST + c0 + nt * 8 + gi]);
                unsigned b1 = f2tf32(Ys[(k0 + ti + 4) * CST + c0 + nt * 8 + gi]);
                mma_tf32(acc[nt], a0, a1, a2, a3, b0, b1);
            }
        }
        // store out (float2)
        #pragma unroll
        for (int nt = 0; nt < 4; nt++) {
            int col = c0 + nt * 8 + 2 * ti;
            *(float2*)&out[xb + (r0 + gi)     * 64 + col] = make_float2(acc[nt][0], acc[nt][1]);
            *(float2*)&out[xb + (r0 + gi + 8) * 64 + col] = make_float2(acc[nt][2], acc[nt][3]);
        }
        // write next Xs from prefetched registers
        if (it < 3) {
            #pragma unroll
            for (int t = 0; t < 4; t++) {
                int q = tid + t * 256;
                float4 v = xq[t];
                v.x *= dsq[t].x; v.y *= dsq[t].y; v.z *= dsq[t].z; v.w *= dsq[t].w;
                *(float4*)&Xn[(q >> 4) * CST + (q & 15) * 4] = v;
            }
        }
        __syncthreads();
    }
}

// ---------------------------------------------------------------------------
// Launch
// ---------------------------------------------------------------------------
extern "C" void kernel_launch(void* const* d_in, const int* in_sizes, int n_in,
                              void* d_out, int out_size)
{
    const float* x   = (const float*)d_in[0];
    const float* ul  = (const float*)d_in[1];
    const float* vl  = (const float*)d_in[2];
    const float* dl  = (const float*)d_in[3];
    const float* ur  = (const float*)d_in[4];
    const float* vr  = (const float*)d_in[5];
    const float* dr  = (const float*)d_in[6];
    const float* dsc = (const float*)d_in[7];
    float* out = (float*)d_out;

    static const int kCaySmem = 4 * 64 * CST * (int)sizeof(float);   // 69632
    cudaFuncSetAttribute(cayley_kernel,
                         cudaFuncAttributeMaxDynamicSharedMemorySize, kCaySmem);
    cayley_kernel<<<4, 1024, kCaySmem>>>(ul, vl, ur, vr);
    combine_kernel<<<2, 256>>>(dl, dr);

    static const int kSmem = 4 * 64 * CST * (int)sizeof(float);      // 69632
    cudaFuncSetAttribute(trans_kernel,
                         cudaFuncAttributeMaxDynamicSharedMemorySize, kSmem);
    trans_kernel<<<2048, 256, kSmem>>>(x, dsc, out);
}

// round 5
// speedup vs baseline: 1.5002x; 1.2083x over previous
#include <cuda_runtime.h>
#include <cuda_bf16.h>

// ---------------------------------------------------------------------------
// out[n] = m_left^T @ (x[n] * diag_scale) @ m_right, n = 0..8191 (64x64 each)
// Identity split for tf32 precision:
//   E_L^T = m_left^T - I,  E_R = m_right - I
//   Y   = Xs + Xs @ E_R ;  out = Y + E_L^T @ Y
// Stage 2 is column-local -> warps own full-column slabs; Y is warp-private.
// Cayley via truncated polynomial: Q = (I+2M+M^2)(I+M^2)(I+M^4), M = A/2.
// ---------------------------------------------------------------------------

__device__ float g_Q[4 * 4096];    // Cayley results: [u_l, v_l, u_r, v_r]
__device__ float g_ELT[4096];      // (m_left^T - I)[l][i]
__device__ float g_ER[4096];       // (m_right  - I)[j][r]

#define CST 68   // smem stride: 68 % 32 == 4 -> (4*gi + ti) conflict-free frags

// ---------------------------------------------------------------------------
// Kernel 1: 4 blocks x 1024 threads; polynomial Cayley with 4 smem matmuls.
// ---------------------------------------------------------------------------
__device__ __forceinline__ void mm64(float* C, const float* A, const float* B,
                                     bool addA, int tid)
{
    int r  = tid >> 4;          // 0..63
    int c0 = (tid & 15) * 4;    // 0..60
    float acc[4];
    if (addA) {
        float4 a4 = *(const float4*)&A[r * CST + c0];
        acc[0] = a4.x; acc[1] = a4.y; acc[2] = a4.z; acc[3] = a4.w;
    } else {
        acc[0] = acc[1] = acc[2] = acc[3] = 0.0f;
    }
    #pragma unroll 8
    for (int k = 0; k < 64; k++) {
        float a = A[r * CST + k];
        float4 b4 = *(const float4*)&B[k * CST + c0];
        acc[0] += a * b4.x; acc[1] += a * b4.y;
        acc[2] += a * b4.z; acc[3] += a * b4.w;
    }
    *(float4*)&C[r * CST + c0] = make_float4(acc[0], acc[1], acc[2], acc[3]);
    __syncthreads();
}

__global__ void __launch_bounds__(1024) cayley_kernel(
    const float* __restrict__ ul, const float* __restrict__ vl,
    const float* __restrict__ ur, const float* __restrict__ vr)
{
    extern __shared__ float cs[];
    float* B0 = cs;                 // M, later L
    float* B1 = cs + 64 * CST;      // m2, later Q
    float* B2 = cs + 2 * 64 * CST;  // m4
    float* B3 = cs + 3 * 64 * CST;  // T
    const float* src = (blockIdx.x == 0) ? ul : (blockIdx.x == 1) ? vl
                     : (blockIdx.x == 2) ? ur : vr;
    int tid = threadIdx.x;

    for (int idx = tid; idx < 4096; idx += 1024) {
        int i = idx >> 6, j = idx & 63;
        float a = 0.0f;
        if (i > j)      a =  src[i * 64 + j];
        else if (i < j) a = -src[j * 64 + i];
        B0[i * CST + j] = 0.5f * a;
    }
    __syncthreads();

    mm64(B1, B0, B0, false, tid);   // m2 = M*M
    mm64(B2, B1, B1, false, tid);   // m4 = m2*m2

    {   // L = I + 2M + m2  (in place over M)
        int r = tid >> 4, c0 = (tid & 15) * 4;
        float4 m  = *(float4*)&B0[r * CST + c0];
        float4 m2 = *(float4*)&B1[r * CST + c0];
        float4 L = make_float4(2.0f * m.x + m2.x, 2.0f * m.y + m2.y,
                               2.0f * m.z + m2.z, 2.0f * m.w + m2.w);
        if (r == c0)     L.x += 1.0f;
        if (r == c0 + 1) L.y += 1.0f;
        if (r == c0 + 2) L.z += 1.0f;
        if (r == c0 + 3) L.w += 1.0f;
        *(float4*)&B0[r * CST + c0] = L;
    }
    __syncthreads();

    mm64(B3, B0, B1, true, tid);    // T = L + L*m2
    mm64(B1, B3, B2, true, tid);    // Q = T + T*m4

    float* dst = g_Q + blockIdx.x * 4096;
    for (int idx = tid; idx < 4096; idx += 1024)
        dst[idx] = B1[(idx >> 6) * CST + (idx & 63)];
}

// ---------------------------------------------------------------------------
// Kernel 2: 2 blocks. Block 0 -> E_L^T, block 1 -> E_R.
// ---------------------------------------------------------------------------
__global__ void __launch_bounds__(256) combine_kernel(
    const float* __restrict__ dl, const float* __restrict__ dr)
{
    __shared__ float Qa[64 * 65], Qb[64 * 65], dsh[64];
    int b = blockIdx.x, tid = threadIdx.x;
    const float* qa = g_Q + (b ? 2 : 0) * 4096;
    const float* qb = g_Q + (b ? 3 : 1) * 4096;
    const float* dg = b ? dr : dl;

    for (int idx = tid; idx < 4096; idx += 256) {
        int i = idx >> 6, j = idx & 63;
        Qa[i * 65 + j] = qa[idx];
        Qb[i * 65 + j] = qb[idx];
    }
    if (tid < 64) dsh[tid] = dg[tid];
    __syncthreads();

    float* dst = b ? g_ER : g_ELT;
    for (int idx = tid; idx < 4096; idx += 256) {
        int row = idx >> 6, col = idx & 63;
        int mi = b ? row : col;
        int mj = b ? col : row;
        float s = 0.0f;
        #pragma unroll 8
        for (int k = 0; k < 64; k++)
            s += Qa[mi * 65 + k] * (dsh[k] * Qb[k * 65 + mj]);
        if (mi == mj) s -= 1.0f;
        dst[idx] = s;
    }
}

// ---------------------------------------------------------------------------
// Main batched transform: tf32 mma.m16n8k8.
// 2 warps per matrix (64x32 slabs), 4 matrices/block concurrent, 2 rounds.
// ---------------------------------------------------------------------------
__device__ __forceinline__ unsigned f2tf32(float f) {
    unsigned u;
    asm("cvt.rna.tf32.f32 %0, %1;" : "=r"(u) : "f"(f));
    return u;
}

__device__ __forceinline__ void mma_tf32(float c[4],
    unsigned a0, unsigned a1, unsigned a2, unsigned a3,
    unsigned b0, unsigned b1)
{
    asm volatile(
        "mma.sync.aligned.m16n8k8.row.col.f32.tf32.tf32.f32 "
        "{%0,%1,%2,%3}, {%4,%5,%6,%7}, {%8,%9}, {%0,%1,%2,%3};\n"
        : "+f"(c[0]), "+f"(c[1]), "+f"(c[2]), "+f"(c[3])
        : "r"(a0), "r"(a1), "r"(a2), "r"(a3), "r"(b0), "r"(b1));
}

__global__ void __launch_bounds__(256, 2) trans_kernel(
    const float* __restrict__ x, const float* __restrict__ dscale,
    float* __restrict__ out)
{
    extern __shared__ float sm[];
    float*    Xs   = sm;                                  // 4 matrices, 64xCST
    unsigned* sELT = (unsigned*)(sm + 4 * 64 * CST);      // E_L^T, tf32, row-major
    unsigned* sERt = sELT + 64 * CST;                     // E_R, tf32, TRANSPOSED

    int tid = threadIdx.x;
    int w = tid >> 5, lane = tid & 31, gi = lane >> 2, ti = lane & 3;
    int g  = w >> 1;          // matrix group 0..3 (2 warps each)
    int c0 = (w & 1) * 32;    // this warp's column half

    for (int idx = tid; idx < 4096; idx += 256) {
        int i = idx >> 6, j = idx & 63;
        sELT[i * CST + j] = f2tf32(g_ELT[idx]);
        sERt[j * CST + i] = f2tf32(g_ER[idx]);   // transposed: [n][k]
    }

    float4 dsq[4];
    #pragma unroll
    for (int t = 0; t < 4; t++) dsq[t] = ((const float4*)dscale)[tid + t * 256];

    int base = blockIdx.x * 8 * 4096;
    __syncthreads();

    #pragma unroll 1
    for (int rnd = 0; rnd < 2; rnd++) {
        // ---- cooperative fill of 4 matrices (coalesced) ----
        const float4* xp = (const float4*)(x + base + rnd * 4 * 4096);
        #pragma unroll
        for (int m = 0; m < 4; m++) {
            float* X = Xs + m * 64 * CST;
            #pragma unroll
            for (int t = 0; t < 4; t++) {
                int q = tid + t * 256;
                float4 v = xp[m * 1024 + q];
                v.x *= dsq[t].x; v.y *= dsq[t].y;
                v.z *= dsq[t].z; v.w *= dsq[t].w;
                *(float4*)&X[(q >> 4) * CST + (q & 15) * 4] = v;
            }
        }
        __syncthreads();

        float*    X  = Xs + g * 64 * CST;
        unsigned* Yt = (unsigned*)X;         // transposed tf32 Y, own cols only
        int xb = base + (rnd * 4 + g) * 4096;

        // ---- acc preload = Xs at C-fragment positions (exact identity) ----
        float acc[4][4][4];
        #pragma unroll
        for (int mt = 0; mt < 4; mt++)
            #pragma unroll
            for (int nt = 0; nt < 4; nt++) {
                int r = 16 * mt + gi, col = c0 + 8 * nt + 2 * ti;
                acc[mt][nt][0] = X[r * CST + col];
                acc[mt][nt][1] = X[r * CST + col + 1];
                acc[mt][nt][2] = X[(r + 8) * CST + col];
                acc[mt][nt][3] = X[(r + 8) * CST + col + 1];
            }

        // ---- Stage 1: acc += Xs @ E_R ----
        #pragma unroll
        for (int kt = 0; kt < 8; kt++) {
            int k0 = kt * 8;
            unsigned b[4][2];
            #pragma unroll
            for (int nt = 0; nt < 4; nt++) {
                b[nt][0] = sERt[(c0 + 8 * nt + gi) * CST + k0 + ti];
                b[nt][1] = sERt[(c0 + 8 * nt + gi) * CST + k0 + ti + 4];
            }
            #pragma unroll
            for (int mt = 0; mt < 4; mt++) {
                int r = 16 * mt + gi;
                unsigned a0 = f2tf32(X[r * CST + k0 + ti]);
                unsigned a1 = f2tf32(X[(r + 8) * CST + k0 + ti]);
                unsigned a2 = f2tf32(X[r * CST + k0 + ti + 4]);
                unsigned a3 = f2tf32(X[(r + 8) * CST + k0 + ti + 4]);
                #pragma unroll
                for (int nt = 0; nt < 4; nt++)
                    mma_tf32(acc[mt][nt], a0, a1, a2, a3, b[nt][0], b[nt][1]);
            }
        }

        // ---- group barrier: both warps done reading X; then write Y ----
        asm volatile("bar.sync %0, 64;" :: "r"(g + 1));

        // write Y transposed+tf32 into own column slab (warp-private)
        #pragma unroll
        for (int mt = 0; mt < 4; mt++)
            #pragma unroll
            for (int nt = 0; nt < 4; nt++) {
                int r = 16 * mt + gi, col = c0 + 8 * nt + 2 * ti;
                Yt[col * CST + r]           = f2tf32(acc[mt][nt][0]);
                Yt[(col + 1) * CST + r]     = f2tf32(acc[mt][nt][1]);
                Yt[col * CST + r + 8]       = f2tf32(acc[mt][nt][2]);
                Yt[(col + 1) * CST + r + 8] = f2tf32(acc[mt][nt][3]);
            }
        __syncwarp();

        // ---- Stage 2: acc += E_L^T @ Y (B from own transposed Y) ----
        #pragma unroll
        for (int kt = 0; kt < 8; kt++) {
            int k0 = kt * 8;
            unsigned b[4][2];
            #pragma unroll
            for (int nt = 0; nt < 4; nt++) {
                b[nt][0] = Yt[(c0 + 8 * nt + gi) * CST + k0 + ti];
                b[nt][1] = Yt[(c0 + 8 * nt + gi) * CST + k0 + ti + 4];
            }
            #pragma unroll
            for (int mt = 0; mt < 4; mt++) {
                int r = 16 * mt + gi;
                unsigned a0 = sELT[r * CST + k0 + ti];
                unsigned a1 = sELT[(r + 8) * CST + k0 + ti];
                unsigned a2 = sELT[r * CST + k0 + ti + 4];
                unsigned a3 = sELT[(r + 8) * CST + k0 + ti + 4];
                #pragma unroll
                for (int nt = 0; nt < 4; nt++)
                    mma_tf32(acc[mt][nt], a0, a1, a2, a3, b[nt][0], b[nt][1]);
            }
        }

        // ---- store ----
        #pragma unroll
        for (int mt = 0; mt < 4; mt++)
            #pragma unroll
            for (int nt = 0; nt < 4; nt++) {
                int r = 16 * mt + gi, col = c0 + 8 * nt + 2 * ti;
                *(float2*)&out[xb + r * 64 + col] =
                    make_float2(acc[mt][nt][0], acc[mt][nt][1]);
                *(float2*)&out[xb + (r + 8) * 64 + col] =
                    make_float2(acc[mt][nt][2], acc[mt][nt][3]);
            }
        __syncthreads();   // Xs reused next round
    }
}

// ---------------------------------------------------------------------------
// Launch
// ---------------------------------------------------------------------------
extern "C" void kernel_launch(void* const* d_in, const int* in_sizes, int n_in,
                              void* d_out, int out_size)
{
    const float* x   = (const float*)d_in[0];
    const float* ul  = (const float*)d_in[1];
    const float* vl  = (const float*)d_in[2];
    const float* dl  = (const float*)d_in[3];
    const float* ur  = (const float*)d_in[4];
    const float* vr  = (const float*)d_in[5];
    const float* dr  = (const float*)d_in[6];
    const float* dsc = (const float*)d_in[7];
    float* out = (float*)d_out;

    static const int kCaySmem = 4 * 64 * CST * (int)sizeof(float);   // 69632
    cudaFuncSetAttribute(cayley_kernel,
                         cudaFuncAttributeMaxDynamicSharedMemorySize, kCaySmem);
    cayley_kernel<<<4, 1024, kCaySmem>>>(ul, vl, ur, vr);
    combine_kernel<<<2, 256>>>(dl, dr);

    static const int kSmem = 6 * 64 * CST * (int)sizeof(float);      // 104448
    cudaFuncSetAttribute(trans_kernel,
                         cudaFuncAttributeMaxDynamicSharedMemorySize, kSmem);
    trans_kernel<<<1024, 256, kSmem>>>(x, dsc, out);
}